// round 1
// baseline (speedup 1.0000x reference)
#include <cuda_runtime.h>

#define BB 8192
#define TT 140
#define HH 64
#define ROWS 32
#define NW 4
#define THREADS 128

struct __align__(16) Smem {
    float2 w0[64][32];    // W_hh0 packed: [k][jpair] -> (W[2jp][k], W[2jp+1][k])
    float2 w1i[64][32];   // W_ih1 packed
    float2 w1h[64][32];   // W_hh1 packed
    float2 h0[ROWS][66];  // duplicated (v,v); row stride 66 float2 = 33 x16B (odd -> conflict-free)
    float2 h1[ROWS][66];
    float  xsh[ROWS * TT];
    float2 wih0p[32];
    float2 b0p[32];
    float2 b1p[32];
    float  wout[64];
    float  ypart[NW][ROWS];
};

__device__ __forceinline__ unsigned long long pack2(float lo, float hi) {
    unsigned long long r;
    asm("mov.b64 %0, {%1, %2};" : "=l"(r) : "f"(lo), "f"(hi));
    return r;
}
__device__ __forceinline__ void unpack2(unsigned long long v, float& lo, float& hi) {
    asm("mov.b64 {%0, %1}, %2;" : "=f"(lo), "=f"(hi) : "l"(v));
}
__device__ __forceinline__ unsigned long long fma2(unsigned long long a,
                                                   unsigned long long b,
                                                   unsigned long long c) {
    unsigned long long d;
    asm("fma.rn.f32x2 %0, %1, %2, %3;" : "=l"(d) : "l"(a), "l"(b), "l"(c));
    return d;
}
__device__ __forceinline__ float fast_tanh(float x) {
    // tanh(x) = 1 - 2/(exp(2x)+1); exact at +/-inf saturation, rel err ~1e-6
    float e = __expf(2.0f * x);
    return 1.0f - __fdividef(2.0f, e + 1.0f);
}

// acc[jp] += sum_k h[row][k] * W[k][jp0+jp], k = 0..63, using packed f32x2
__device__ __forceinline__ void matvec_acc(unsigned long long acc[8],
                                           const float2 (&W)[64][32],
                                           const float2 (&hbuf)[ROWS][66],
                                           int lane, int jp0) {
#pragma unroll 4
    for (int k = 0; k < 64; k += 2) {
        ulonglong2 hh = *reinterpret_cast<const ulonglong2*>(&hbuf[lane][k]);
        const ulonglong2* wk  = reinterpret_cast<const ulonglong2*>(&W[k][jp0]);
        const ulonglong2* wk1 = reinterpret_cast<const ulonglong2*>(&W[k + 1][jp0]);
        ulonglong2 a0 = wk[0],  a1 = wk[1],  a2 = wk[2],  a3 = wk[3];
        ulonglong2 c0 = wk1[0], c1 = wk1[1], c2 = wk1[2], c3 = wk1[3];
        acc[0] = fma2(hh.x, a0.x, acc[0]); acc[1] = fma2(hh.x, a0.y, acc[1]);
        acc[2] = fma2(hh.x, a1.x, acc[2]); acc[3] = fma2(hh.x, a1.y, acc[3]);
        acc[4] = fma2(hh.x, a2.x, acc[4]); acc[5] = fma2(hh.x, a2.y, acc[5]);
        acc[6] = fma2(hh.x, a3.x, acc[6]); acc[7] = fma2(hh.x, a3.y, acc[7]);
        acc[0] = fma2(hh.y, c0.x, acc[0]); acc[1] = fma2(hh.y, c0.y, acc[1]);
        acc[2] = fma2(hh.y, c1.x, acc[2]); acc[3] = fma2(hh.y, c1.y, acc[3]);
        acc[4] = fma2(hh.y, c2.x, acc[4]); acc[5] = fma2(hh.y, c2.y, acc[5]);
        acc[6] = fma2(hh.y, c3.x, acc[6]); acc[7] = fma2(hh.y, c3.y, acc[7]);
    }
}

__global__ void __launch_bounds__(THREADS) rnn_kernel(
    const float* __restrict__ x, const float* __restrict__ h_state,
    const float* __restrict__ Wih0, const float* __restrict__ Whh0,
    const float* __restrict__ bih0, const float* __restrict__ bhh0,
    const float* __restrict__ Wih1, const float* __restrict__ Whh1,
    const float* __restrict__ bih1, const float* __restrict__ bhh1,
    const float* __restrict__ Wout, const float* __restrict__ bout,
    float* __restrict__ out) {
    extern __shared__ char smraw[];
    Smem* sm = reinterpret_cast<Smem*>(smraw);
    const int tid  = threadIdx.x;
    const int lane = tid & 31;
    const int w    = tid >> 5;
    const int jp0  = w * 8;
    const int row0 = blockIdx.x * ROWS;

    // ---- prologue: stage x, weights (transposed+paired), h-state, vectors ----
    for (int i = tid; i < ROWS * TT; i += THREADS)
        sm->xsh[i] = x[row0 * TT + i];
    for (int i = tid; i < 2048; i += THREADS) {
        int k = i >> 5, jp = i & 31;
        sm->w0[k][jp]  = make_float2(Whh0[(2 * jp) * HH + k], Whh0[(2 * jp + 1) * HH + k]);
        sm->w1i[k][jp] = make_float2(Wih1[(2 * jp) * HH + k], Wih1[(2 * jp + 1) * HH + k]);
        sm->w1h[k][jp] = make_float2(Whh1[(2 * jp) * HH + k], Whh1[(2 * jp + 1) * HH + k]);
    }
    for (int i = tid; i < ROWS * HH; i += THREADS) {
        int r = i >> 6, k = i & 63;
        float v0 = h_state[(row0 + r) * HH + k];
        float v1 = h_state[(BB + row0 + r) * HH + k];
        sm->h0[r][k] = make_float2(v0, v0);
        sm->h1[r][k] = make_float2(v1, v1);
    }
    if (tid < 32) {
        int jp = tid;
        sm->wih0p[jp] = make_float2(Wih0[2 * jp], Wih0[2 * jp + 1]);
        sm->b0p[jp] = make_float2(bih0[2 * jp] + bhh0[2 * jp],
                                  bih0[2 * jp + 1] + bhh0[2 * jp + 1]);
        sm->b1p[jp] = make_float2(bih1[2 * jp] + bhh1[2 * jp],
                                  bih1[2 * jp + 1] + bhh1[2 * jp + 1]);
        sm->wout[2 * jp]     = Wout[2 * jp];
        sm->wout[2 * jp + 1] = Wout[2 * jp + 1];
    }
    const float bo = bout[0];
    __syncthreads();

    // ---- recurrence ----
    for (int t = 0; t < TT; ++t) {
        unsigned long long acc[8];
        // layer 0: acc_j = x_t*Wih0_j + (b_ih0+b_hh0)_j + sum_k h0_k * Whh0[j][k]
        {
            float xv = sm->xsh[lane * TT + t];
            unsigned long long xp = pack2(xv, xv);
            const unsigned long long* wi = reinterpret_cast<const unsigned long long*>(sm->wih0p);
            const unsigned long long* bb = reinterpret_cast<const unsigned long long*>(sm->b0p);
#pragma unroll
            for (int i = 0; i < 8; ++i) acc[i] = fma2(xp, wi[jp0 + i], bb[jp0 + i]);
        }
        matvec_acc(acc, sm->w0, sm->h0, lane, jp0);
        float hv[16];
#pragma unroll
        for (int i = 0; i < 8; ++i) {
            float lo, hi;
            unpack2(acc[i], lo, hi);
            hv[2 * i]     = fast_tanh(lo);
            hv[2 * i + 1] = fast_tanh(hi);
        }
        __syncthreads();  // (A) all reads of h0_{t-1} complete
#pragma unroll
        for (int i = 0; i < 16; ++i)
            sm->h0[lane][2 * jp0 + i] = make_float2(hv[i], hv[i]);
        __syncthreads();  // (B) h0n visible

        // layer 1: acc_j = (b_ih1+b_hh1)_j + sum_k h0n_k*Wih1[j][k] + sum_k h1_k*Whh1[j][k]
        {
            const unsigned long long* bb = reinterpret_cast<const unsigned long long*>(sm->b1p);
#pragma unroll
            for (int i = 0; i < 8; ++i) acc[i] = bb[jp0 + i];
        }
        matvec_acc(acc, sm->w1i, sm->h0, lane, jp0);
        matvec_acc(acc, sm->w1h, sm->h1, lane, jp0);
        float yp = 0.0f;
#pragma unroll
        for (int i = 0; i < 8; ++i) {
            float lo, hi;
            unpack2(acc[i], lo, hi);
            lo = fast_tanh(lo);
            hi = fast_tanh(hi);
            hv[2 * i]     = lo;
            hv[2 * i + 1] = hi;
            yp += lo * sm->wout[2 * (jp0 + i)] + hi * sm->wout[2 * (jp0 + i) + 1];
        }
        __syncthreads();  // (C) all reads of h1_{t-1} complete
#pragma unroll
        for (int i = 0; i < 16; ++i)
            sm->h1[lane][2 * jp0 + i] = make_float2(hv[i], hv[i]);
        sm->ypart[w][lane] = yp;
        __syncthreads();  // (D) h1n + partials visible
        if (w == 0) {
            float y = sm->ypart[0][lane] + sm->ypart[1][lane] +
                      sm->ypart[2][lane] + sm->ypart[3][lane] + bo;
            sm->xsh[lane * TT + t] = y;  // x[.,t] already consumed; reuse as y buffer
        }
    }
    __syncthreads();

    // ---- epilogue: flush y (coalesced) and h_final ----
    for (int i = tid; i < ROWS * TT; i += THREADS)
        out[row0 * TT + i] = sm->xsh[i];
    const int BT = BB * TT;
    for (int i = tid; i < ROWS * HH; i += THREADS) {
        int r = i >> 6, k = i & 63;
        out[BT + (row0 + r) * HH + k]           = sm->h0[r][k].x;
        out[BT + BB * HH + (row0 + r) * HH + k] = sm->h1[r][k].x;
    }
}

extern "C" void kernel_launch(void* const* d_in, const int* in_sizes, int n_in,
                              void* d_out, int out_size) {
    (void)in_sizes; (void)n_in; (void)out_size;
    const float* x    = (const float*)d_in[0];
    const float* hs   = (const float*)d_in[1];
    const float* Wih0 = (const float*)d_in[2];
    const float* Whh0 = (const float*)d_in[3];
    const float* bih0 = (const float*)d_in[4];
    const float* bhh0 = (const float*)d_in[5];
    const float* Wih1 = (const float*)d_in[6];
    const float* Whh1 = (const float*)d_in[7];
    const float* bih1 = (const float*)d_in[8];
    const float* bhh1 = (const float*)d_in[9];
    const float* Wout = (const float*)d_in[10];
    const float* bout = (const float*)d_in[11];
    float* out = (float*)d_out;

    cudaFuncSetAttribute(rnn_kernel, cudaFuncAttributeMaxDynamicSharedMemorySize,
                         (int)sizeof(Smem));
    rnn_kernel<<<BB / ROWS, THREADS, sizeof(Smem)>>>(
        x, hs, Wih0, Whh0, bih0, bhh0, Wih1, Whh1, bih1, bhh1, Wout, bout, out);
}

// round 2
// speedup vs baseline: 1.6325x; 1.6325x over previous
#include <cuda_runtime.h>

#define BB 8192
#define TT 140
#define HH 64
#define ROWS 64
#define THREADS 128
#define HS 68   // h row stride in floats: 68 mod 32 = 4 -> conflict-free float4 ld/st

typedef unsigned long long ull;

struct __align__(16) Smem {
    float2 w0[64][32];    // W_hh0 packed: [k][jp] = (W[2jp][k], W[2jp+1][k])
    float2 w1i[64][32];   // W_ih1 packed
    float2 w1h[64][32];   // W_hh1 packed
    float  h0[2][ROWS][HS];  // double-buffered, non-duplicated
    float  h1[2][ROWS][HS];
    float2 wih0p[32];
    float2 b0p[32];
    float2 b1p[32];
    float  wout[64];
    float  ypart[2][4][ROWS];
};

__device__ __forceinline__ ull pack2(float lo, float hi) {
    ull r;
    asm("mov.b64 %0, {%1, %2};" : "=l"(r) : "f"(lo), "f"(hi));
    return r;
}
__device__ __forceinline__ void unpack2(ull v, float& lo, float& hi) {
    asm("mov.b64 {%0, %1}, %2;" : "=f"(lo), "=f"(hi) : "l"(v));
}
__device__ __forceinline__ ull fma2(ull a, ull b, ull c) {
    ull d;
    asm("fma.rn.f32x2 %0, %1, %2, %3;" : "=l"(d) : "l"(a), "l"(b), "l"(c));
    return d;
}
__device__ __forceinline__ float fast_tanh(float x) {
    float e = __expf(2.0f * x);
    return 1.0f - __fdividef(2.0f, e + 1.0f);
}

// acc{0,1}[jp] += sum_k h{r0,r1}[k] * W[k][jp0+jp]  (k = 0..63, packed f32x2)
__device__ __forceinline__ void matvec2(ull (&acc0)[8], ull (&acc1)[8],
                                        const float2 (&W)[64][32],
                                        const float* __restrict__ hr0,
                                        const float* __restrict__ hr1, int jp0) {
#pragma unroll 4
    for (int k4 = 0; k4 < 64; k4 += 4) {
        float4 a = *reinterpret_cast<const float4*>(hr0 + k4);
        float4 b = *reinterpret_cast<const float4*>(hr1 + k4);
        ull ap[4], bp[4];
        ap[0] = pack2(a.x, a.x); ap[1] = pack2(a.y, a.y);
        ap[2] = pack2(a.z, a.z); ap[3] = pack2(a.w, a.w);
        bp[0] = pack2(b.x, b.x); bp[1] = pack2(b.y, b.y);
        bp[2] = pack2(b.z, b.z); bp[3] = pack2(b.w, b.w);
#pragma unroll
        for (int kk = 0; kk < 4; ++kk) {
            const ulonglong2* wk = reinterpret_cast<const ulonglong2*>(&W[k4 + kk][jp0]);
            ulonglong2 w01 = wk[0], w23 = wk[1], w45 = wk[2], w67 = wk[3];
            acc0[0] = fma2(ap[kk], w01.x, acc0[0]); acc0[1] = fma2(ap[kk], w01.y, acc0[1]);
            acc0[2] = fma2(ap[kk], w23.x, acc0[2]); acc0[3] = fma2(ap[kk], w23.y, acc0[3]);
            acc0[4] = fma2(ap[kk], w45.x, acc0[4]); acc0[5] = fma2(ap[kk], w45.y, acc0[5]);
            acc0[6] = fma2(ap[kk], w67.x, acc0[6]); acc0[7] = fma2(ap[kk], w67.y, acc0[7]);
            acc1[0] = fma2(bp[kk], w01.x, acc1[0]); acc1[1] = fma2(bp[kk], w01.y, acc1[1]);
            acc1[2] = fma2(bp[kk], w23.x, acc1[2]); acc1[3] = fma2(bp[kk], w23.y, acc1[3]);
            acc1[4] = fma2(bp[kk], w45.x, acc1[4]); acc1[5] = fma2(bp[kk], w45.y, acc1[5]);
            acc1[6] = fma2(bp[kk], w67.x, acc1[6]); acc1[7] = fma2(bp[kk], w67.y, acc1[7]);
        }
    }
}

__global__ void __launch_bounds__(THREADS, 1) rnn_kernel(
    const float* __restrict__ x, const float* __restrict__ h_state,
    const float* __restrict__ Wih0, const float* __restrict__ Whh0,
    const float* __restrict__ bih0, const float* __restrict__ bhh0,
    const float* __restrict__ Wih1, const float* __restrict__ Whh1,
    const float* __restrict__ bih1, const float* __restrict__ bhh1,
    const float* __restrict__ Wout, const float* __restrict__ bout,
    float* __restrict__ out) {
    extern __shared__ char smraw[];
    Smem* sm = reinterpret_cast<Smem*>(smraw);
    const int tid  = threadIdx.x;
    const int lane = tid & 31;
    const int w    = tid >> 5;
    const int jp0  = w * 8;
    const int row0 = blockIdx.x * ROWS;

    // ---- prologue ----
    for (int i = tid; i < 2048; i += THREADS) {
        int k = i >> 5, jp = i & 31;
        sm->w0[k][jp]  = make_float2(Whh0[(2 * jp) * HH + k], Whh0[(2 * jp + 1) * HH + k]);
        sm->w1i[k][jp] = make_float2(Wih1[(2 * jp) * HH + k], Wih1[(2 * jp + 1) * HH + k]);
        sm->w1h[k][jp] = make_float2(Whh1[(2 * jp) * HH + k], Whh1[(2 * jp + 1) * HH + k]);
    }
    for (int i = tid; i < ROWS * HH; i += THREADS) {
        int r = i >> 6, k = i & 63;
        sm->h0[0][r][k] = h_state[(row0 + r) * HH + k];
        sm->h1[0][r][k] = h_state[(BB + row0 + r) * HH + k];
    }
    if (tid < 32) {
        int jp = tid;
        sm->wih0p[jp] = make_float2(Wih0[2 * jp], Wih0[2 * jp + 1]);
        sm->b0p[jp] = make_float2(bih0[2 * jp] + bhh0[2 * jp],
                                  bih0[2 * jp + 1] + bhh0[2 * jp + 1]);
        sm->b1p[jp] = make_float2(bih1[2 * jp] + bhh1[2 * jp],
                                  bih1[2 * jp + 1] + bhh1[2 * jp + 1]);
        sm->wout[2 * jp]     = Wout[2 * jp];
        sm->wout[2 * jp + 1] = Wout[2 * jp + 1];
    }
    const float bo = bout[0];
    const float* gx0 = x + (row0 + lane) * TT;
    const float* gx1 = gx0 + 32 * TT;
    float xv0 = gx0[0], xv1 = gx1[0];
    __syncthreads();

    int p = 0, q = 0;
    // ---- recurrence: ONE barrier per step ----
    for (int t = 0; t < TT; ++t) {
        float xc0 = xv0, xc1 = xv1;
        int tn = (t + 1 < TT) ? t + 1 : TT - 1;
        xv0 = gx0[tn]; xv1 = gx1[tn];  // prefetch next step's x

        // layer 0
        ull acc0[8], acc1[8];
        {
            ull xp0 = pack2(xc0, xc0), xp1 = pack2(xc1, xc1);
            const ull* wi  = reinterpret_cast<const ull*>(sm->wih0p);
            const ull* bb0 = reinterpret_cast<const ull*>(sm->b0p);
#pragma unroll
            for (int i = 0; i < 8; ++i) {
                ull wv = wi[jp0 + i], bv = bb0[jp0 + i];
                acc0[i] = fma2(xp0, wv, bv);
                acc1[i] = fma2(xp1, wv, bv);
            }
        }
        matvec2(acc0, acc1, sm->w0, sm->h0[p][lane], sm->h0[p][lane + 32], jp0);
        float hv0[16], hv1[16];
#pragma unroll
        for (int i = 0; i < 8; ++i) {
            float lo, hi;
            unpack2(acc0[i], lo, hi);
            hv0[2 * i] = fast_tanh(lo); hv0[2 * i + 1] = fast_tanh(hi);
            unpack2(acc1[i], lo, hi);
            hv1[2 * i] = fast_tanh(lo); hv1[2 * i + 1] = fast_tanh(hi);
        }
        const int pn = p ^ 1;
#pragma unroll
        for (int s = 0; s < 4; ++s) {
            *reinterpret_cast<float4*>(&sm->h0[pn][lane][2 * jp0 + 4 * s]) =
                make_float4(hv0[4 * s], hv0[4 * s + 1], hv0[4 * s + 2], hv0[4 * s + 3]);
            *reinterpret_cast<float4*>(&sm->h0[pn][lane + 32][2 * jp0 + 4 * s]) =
                make_float4(hv1[4 * s], hv1[4 * s + 1], hv1[4 * s + 2], hv1[4 * s + 3]);
        }
        __syncthreads();  // the only barrier per step

        // delayed y-reduce for step t-1 (ypart other buffer, protected by this barrier)
        if (t > 0 && w < 2) {
            int r = w * 32 + lane;
            float yv = sm->ypart[q ^ 1][0][r] + sm->ypart[q ^ 1][1][r] +
                       sm->ypart[q ^ 1][2][r] + sm->ypart[q ^ 1][3][r] + bo;
            out[(row0 + r) * TT + (t - 1)] = yv;
        }

        // layer 1
        {
            const ull* bb1 = reinterpret_cast<const ull*>(sm->b1p);
#pragma unroll
            for (int i = 0; i < 8; ++i) { acc0[i] = bb1[jp0 + i]; acc1[i] = acc0[i]; }
        }
        matvec2(acc0, acc1, sm->w1i, sm->h0[pn][lane], sm->h0[pn][lane + 32], jp0);
        matvec2(acc0, acc1, sm->w1h, sm->h1[p][lane], sm->h1[p][lane + 32], jp0);
        float yp0 = 0.0f, yp1 = 0.0f;
#pragma unroll
        for (int i = 0; i < 8; ++i) {
            float lo, hi;
            unpack2(acc0[i], lo, hi);
            lo = fast_tanh(lo); hi = fast_tanh(hi);
            hv0[2 * i] = lo; hv0[2 * i + 1] = hi;
            yp0 += lo * sm->wout[2 * (jp0 + i)] + hi * sm->wout[2 * (jp0 + i) + 1];
            unpack2(acc1[i], lo, hi);
            lo = fast_tanh(lo); hi = fast_tanh(hi);
            hv1[2 * i] = lo; hv1[2 * i + 1] = hi;
            yp1 += lo * sm->wout[2 * (jp0 + i)] + hi * sm->wout[2 * (jp0 + i) + 1];
        }
#pragma unroll
        for (int s = 0; s < 4; ++s) {
            *reinterpret_cast<float4*>(&sm->h1[pn][lane][2 * jp0 + 4 * s]) =
                make_float4(hv0[4 * s], hv0[4 * s + 1], hv0[4 * s + 2], hv0[4 * s + 3]);
            *reinterpret_cast<float4*>(&sm->h1[pn][lane + 32][2 * jp0 + 4 * s]) =
                make_float4(hv1[4 * s], hv1[4 * s + 1], hv1[4 * s + 2], hv1[4 * s + 3]);
        }
        sm->ypart[q][w][lane]      = yp0;
        sm->ypart[q][w][lane + 32] = yp1;
        p = pn; q ^= 1;
    }
    __syncthreads();

    // final y (t = TT-1)
    if (w < 2) {
        int r = w * 32 + lane;
        float yv = sm->ypart[q ^ 1][0][r] + sm->ypart[q ^ 1][1][r] +
                   sm->ypart[q ^ 1][2][r] + sm->ypart[q ^ 1][3][r] + bo;
        out[(row0 + r) * TT + (TT - 1)] = yv;
    }
    // h_final
    const int BT = BB * TT;
    for (int i = tid; i < ROWS * HH; i += THREADS) {
        int r = i >> 6, k = i & 63;
        out[BT + (row0 + r) * HH + k]           = sm->h0[p][r][k];
        out[BT + BB * HH + (row0 + r) * HH + k] = sm->h1[p][r][k];
    }
}

extern "C" void kernel_launch(void* const* d_in, const int* in_sizes, int n_in,
                              void* d_out, int out_size) {
    (void)in_sizes; (void)n_in; (void)out_size;
    const float* x    = (const float*)d_in[0];
    const float* hs   = (const float*)d_in[1];
    const float* Wih0 = (const float*)d_in[2];
    const float* Whh0 = (const float*)d_in[3];
    const float* bih0 = (const float*)d_in[4];
    const float* bhh0 = (const float*)d_in[5];
    const float* Wih1 = (const float*)d_in[6];
    const float* Whh1 = (const float*)d_in[7];
    const float* bih1 = (const float*)d_in[8];
    const float* bhh1 = (const float*)d_in[9];
    const float* Wout = (const float*)d_in[10];
    const float* bout = (const float*)d_in[11];
    float* out = (float*)d_out;

    cudaFuncSetAttribute(rnn_kernel, cudaFuncAttributeMaxDynamicSharedMemorySize,
                         (int)sizeof(Smem));
    rnn_kernel<<<BB / ROWS, THREADS, sizeof(Smem)>>>(
        x, hs, Wih0, Whh0, bih0, bhh0, Wih1, Whh1, bih1, bhh1, Wout, bout, out);
}